// round 9
// baseline (speedup 1.0000x reference)
#include <cuda_runtime.h>
#include <cuda_fp16.h>
#include <mma.h>
#include <cstdint>

using namespace nvcuda;

// ---------------- problem constants ----------------
#define BATCH   256
#define INSTRS  64
#define TOKENS  16
#define HID     256
#define EMB     256
#define FOURH   1024
#define KTOT    512
#define NTOK    (BATCH*INSTRS)   // 16384

// ---------------- GEMM tile config (fp16 m16n16k16, BK=128, 2-stage) ----------------
#define BM 128
#define BN 64
#define BK 128
#define LDSH 136                 // BK + 8 pad halfs (272B rows, /8 elems ok for wmma)
#define NK  (KTOT/BK)            // 4
#define CLD 68                   // epilogue Cs stride (floats)

// smem layout (bytes), identical for both step kernels:
//  As [2][128*136]h = 69632 @ 0       (Cs float[128][68]=34816 overlays As)
//  Bs [2][64*136]h  = 34816 @ 69632
//  Aidx int[128]           @ 104448
//  Arow ptr[128]           @ 104960
#define BS_OFF   69632
#define AIDX_OFF 104448
#define AROW_OFF 104960
#define SMEM_BYTES 105984

// ---------------- device state ----------------
// h ping-ponged by step parity: step t reads h[(t&1)^1], writes h[t&1].
__device__ __half g_h_tok[2][(size_t)NTOK * HID];
__device__ float  g_c_tok[(size_t)NTOK * HID];
__device__ __half g_h_ins[2][(size_t)BATCH * HID];
__device__ float  g_c_ins[(size_t)BATCH * HID];
__device__ __half g_instr_repr[(size_t)NTOK * HID];
__device__ int    g_perm_tok[NTOK];
__device__ int    g_cnt_tok[TOKENS];
__device__ int    g_perm_ins[BATCH];
__device__ int    g_cnt_ins[INSTRS];
// pre-converted fp16 operands
__device__ __half g_emb_h[(size_t)4096 * EMB];
__device__ __half g_W_tok[(size_t)FOURH * KTOT];   // [jp][512], gate-interleaved
__device__ __half g_W_ins[(size_t)FOURH * KTOT];

#define CP_ASYNC16(dst, src) \
    asm volatile("cp.async.cg.shared.global [%0], [%1], 16;" :: "r"(dst), "l"(src))
#define CP_COMMIT  asm volatile("cp.async.commit_group;")
#define CP_WAIT0   asm volatile("cp.async.wait_group 0;")

// fast, accurate-enough sigmoid/tanh (__expf rel err ~1e-6; tanh clamped vs inf/inf)
__device__ __forceinline__ float fsig(float x) { return 1.0f / (1.0f + __expf(-x)); }
__device__ __forceinline__ float ftanh(float x) {
    x = fminf(fmaxf(x, -15.0f), 15.0f);
    float e = __expf(2.0f * x);
    return (e - 1.0f) / (e + 1.0f);
}

// ================= token phase: round-5 structure, BK=128 =================
__global__ void __launch_bounds__(256)
tok_step(int t, const int* __restrict__ tok,
         const float* __restrict__ bias, const int* __restrict__ ntok)
{
    if (blockIdx.x * BM >= g_cnt_tok[t]) return;

    extern __shared__ char smraw[];
    __half*        As   = (__half*)smraw;
    __half*        Bs   = (__half*)(smraw + BS_OFF);
    int*           Aidx = (int*)(smraw + AIDX_OFF);
    const __half** Arow = (const __half**)(smraw + AROW_OFF);
    float*         Cs   = (float*)smraw;   // overlay

    const int m0  = blockIdx.x * BM;
    const int n0  = blockIdx.y * BN;
    const int tid = threadIdx.x;
    const int wp  = t & 1;
    const int rp  = wp ^ 1;

    const __half* hbase = g_h_tok[rp];

    for (int r = tid; r < BM; r += 256) {
        int n = g_perm_tok[m0 + r];
        Aidx[r] = n;
        Arow[r] = g_emb_h + (size_t)__ldg(&tok[n * TOKENS + t]) * EMB;
    }
    __syncthreads();

    auto issue = [&](int kt, int buf) {
        __half* Ad = As + buf * BM * LDSH;
        // A tile: 128x128 half = 2048 x 16B chunks, 8/thread
#pragma unroll
        for (int i = 0; i < 8; ++i) {
            int c  = tid + i * 256;
            int r  = c >> 4;             // 16 chunks/row
            int c8 = (c & 15) << 3;
            const __half* src = (kt < 2)
                ? Arow[r] + kt * BK + c8
                : hbase + (size_t)Aidx[r] * HID + (kt - 2) * BK + c8;
            uint32_t dst = (uint32_t)__cvta_generic_to_shared(Ad + r * LDSH + c8);
            CP_ASYNC16(dst, src);
        }
        __half* Bd = Bs + buf * BN * LDSH;
        // B tile: 64x128 half = 1024 chunks, 4/thread
#pragma unroll
        for (int i = 0; i < 4; ++i) {
            int c  = tid + i * 256;
            int r  = c >> 4;
            int c8 = (c & 15) << 3;
            const __half* src = g_W_tok + (size_t)(n0 + r) * KTOT + kt * BK + c8;
            uint32_t dst = (uint32_t)__cvta_generic_to_shared(Bd + r * LDSH + c8);
            CP_ASYNC16(dst, src);
        }
        CP_COMMIT;
    };

    wmma::fragment<wmma::accumulator, 16, 16, 16, float> cf[2][2];
#pragma unroll
    for (int mi = 0; mi < 2; ++mi)
#pragma unroll
        for (int ni = 0; ni < 2; ++ni)
            wmma::fill_fragment(cf[mi][ni], 0.0f);

    const int warp = tid >> 5;
    const int wm   = warp >> 1;
    const int wn   = warp & 1;

    const int nk_eff = (t == 0) ? 2 : NK;   // h==0 at t=0: skip h half of K

    issue(0, 0);
    for (int kt = 0; kt < nk_eff; ++kt) {
        CP_WAIT0;
        __syncthreads();
        if (kt + 1 < nk_eff) issue(kt + 1, (kt + 1) & 1);
        const __half* Ab = As + (kt & 1) * BM * LDSH;
        const __half* Bb = Bs + (kt & 1) * BN * LDSH;
#pragma unroll
        for (int kk = 0; kk < BK; kk += 16) {
            wmma::fragment<wmma::matrix_a, 16, 16, 16, __half, wmma::row_major> a[2];
            wmma::fragment<wmma::matrix_b, 16, 16, 16, __half, wmma::col_major> b[2];
#pragma unroll
            for (int mi = 0; mi < 2; ++mi)
                wmma::load_matrix_sync(a[mi], Ab + (wm * 32 + mi * 16) * LDSH + kk, LDSH);
#pragma unroll
            for (int ni = 0; ni < 2; ++ni)
                wmma::load_matrix_sync(b[ni], Bb + (wn * 32 + ni * 16) * LDSH + kk, LDSH);
#pragma unroll
            for (int mi = 0; mi < 2; ++mi)
#pragma unroll
                for (int ni = 0; ni < 2; ++ni)
                    wmma::mma_sync(cf[mi][ni], a[mi], b[ni], cf[mi][ni]);
        }
    }

    __syncthreads();
#pragma unroll
    for (int mi = 0; mi < 2; ++mi)
#pragma unroll
        for (int ni = 0; ni < 2; ++ni)
            wmma::store_matrix_sync(&Cs[(wm * 32 + mi * 16) * CLD + wn * 32 + ni * 16],
                                    cf[mi][ni], CLD, wmma::mem_row_major);
    __syncthreads();

    {
        int r = tid >> 1;
        int n = Aidx[r];
        int L = __ldg(&ntok[n]);
        if (t < L) {
            __half* hp = g_h_tok[wp];
            float*  cp = g_c_tok;
            int dg0 = (n0 >> 2) + (tid & 1) * 8;
#pragma unroll
            for (int i = 0; i < 8; ++i) {
                int dl = (tid & 1) * 8 + i;
                int dg = dg0 + i;
                float gi = Cs[r * CLD + dl * 4 + 0] + __ldg(&bias[dg]);
                float gf = Cs[r * CLD + dl * 4 + 1] + __ldg(&bias[256 + dg]);
                float gg = Cs[r * CLD + dl * 4 + 2] + __ldg(&bias[512 + dg]);
                float go = Cs[r * CLD + dl * 4 + 3] + __ldg(&bias[768 + dg]);
                float i_ = fsig(gi);
                float f_ = fsig(gf);
                float g_ = ftanh(gg);
                float o_ = fsig(go);
                size_t idx = (size_t)n * HID + dg;
                float cn = f_ * cp[idx] + i_ * g_;
                cp[idx] = cn;
                hp[idx] = __float2half_rn(o_ * ftanh(cn));
            }
        }
    }
}

// ================= instr phase: 64 graph launches, BK=128 =================
__global__ void __launch_bounds__(256)
ins_step(int s, const float* __restrict__ bias, const int* __restrict__ ninstr)
{
    if (blockIdx.x * BM >= g_cnt_ins[s]) return;

    extern __shared__ char smraw[];
    __half* As   = (__half*)smraw;
    __half* Bs   = (__half*)(smraw + BS_OFF);
    int*    Aidx = (int*)(smraw + AIDX_OFF);
    float*  Cs   = (float*)smraw;   // overlay

    const int m0  = blockIdx.x * BM;
    const int n0  = blockIdx.y * BN;
    const int tid = threadIdx.x;
    const int wp  = s & 1;
    const int rp  = wp ^ 1;

    const __half* hbase = g_h_ins[rp];

    for (int r = tid; r < BM; r += 256) Aidx[r] = g_perm_ins[m0 + r];
    __syncthreads();

    auto issue = [&](int kt, int buf) {
        __half* Ad = As + buf * BM * LDSH;
#pragma unroll
        for (int i = 0; i < 8; ++i) {
            int c  = tid + i * 256;
            int r  = c >> 4;
            int c8 = (c & 15) << 3;
            int n  = Aidx[r];
            const __half* src = (kt < 2)
                ? g_instr_repr + ((size_t)n * INSTRS + s) * HID + kt * BK + c8
                : hbase + (size_t)n * HID + (kt - 2) * BK + c8;
            uint32_t dst = (uint32_t)__cvta_generic_to_shared(Ad + r * LDSH + c8);
            CP_ASYNC16(dst, src);
        }
        __half* Bd = Bs + buf * BN * LDSH;
#pragma unroll
        for (int i = 0; i < 4; ++i) {
            int c  = tid + i * 256;
            int r  = c >> 4;
            int c8 = (c & 15) << 3;
            const __half* src = g_W_ins + (size_t)(n0 + r) * KTOT + kt * BK + c8;
            uint32_t dst = (uint32_t)__cvta_generic_to_shared(Bd + r * LDSH + c8);
            CP_ASYNC16(dst, src);
        }
        CP_COMMIT;
    };

    wmma::fragment<wmma::accumulator, 16, 16, 16, float> cf[2][2];
#pragma unroll
    for (int mi = 0; mi < 2; ++mi)
#pragma unroll
        for (int ni = 0; ni < 2; ++ni)
            wmma::fill_fragment(cf[mi][ni], 0.0f);

    const int warp = tid >> 5;
    const int wm   = warp >> 1;
    const int wn   = warp & 1;

    const int nk_eff = (s == 0) ? 2 : NK;   // h==0 at s=0

    issue(0, 0);
    for (int kt = 0; kt < nk_eff; ++kt) {
        CP_WAIT0;
        __syncthreads();
        if (kt + 1 < nk_eff) issue(kt + 1, (kt + 1) & 1);
        const __half* Ab = As + (kt & 1) * BM * LDSH;
        const __half* Bb = Bs + (kt & 1) * BN * LDSH;
#pragma unroll
        for (int kk = 0; kk < BK; kk += 16) {
            wmma::fragment<wmma::matrix_a, 16, 16, 16, __half, wmma::row_major> a[2];
            wmma::fragment<wmma::matrix_b, 16, 16, 16, __half, wmma::col_major> b[2];
#pragma unroll
            for (int mi = 0; mi < 2; ++mi)
                wmma::load_matrix_sync(a[mi], Ab + (wm * 32 + mi * 16) * LDSH + kk, LDSH);
#pragma unroll
            for (int ni = 0; ni < 2; ++ni)
                wmma::load_matrix_sync(b[ni], Bb + (wn * 32 + ni * 16) * LDSH + kk, LDSH);
#pragma unroll
            for (int mi = 0; mi < 2; ++mi)
#pragma unroll
                for (int ni = 0; ni < 2; ++ni)
                    wmma::mma_sync(cf[mi][ni], a[mi], b[ni], cf[mi][ni]);
        }
    }

    __syncthreads();
#pragma unroll
    for (int mi = 0; mi < 2; ++mi)
#pragma unroll
        for (int ni = 0; ni < 2; ++ni)
            wmma::store_matrix_sync(&Cs[(wm * 32 + mi * 16) * CLD + wn * 32 + ni * 16],
                                    cf[mi][ni], CLD, wmma::mem_row_major);
    __syncthreads();

    {
        int r = tid >> 1;
        int n = Aidx[r];
        int L = __ldg(&ninstr[n]);
        if (s < L) {
            __half* hp = g_h_ins[wp];
            float*  cp = g_c_ins;
            int dg0 = (n0 >> 2) + (tid & 1) * 8;
#pragma unroll
            for (int i = 0; i < 8; ++i) {
                int dl = (tid & 1) * 8 + i;
                int dg = dg0 + i;
                float gi = Cs[r * CLD + dl * 4 + 0] + __ldg(&bias[dg]);
                float gf = Cs[r * CLD + dl * 4 + 1] + __ldg(&bias[256 + dg]);
                float gg = Cs[r * CLD + dl * 4 + 2] + __ldg(&bias[512 + dg]);
                float go = Cs[r * CLD + dl * 4 + 3] + __ldg(&bias[768 + dg]);
                float i_ = fsig(gi);
                float f_ = fsig(gf);
                float g_ = ftanh(gg);
                float o_ = fsig(go);
                size_t idx = (size_t)n * HID + dg;
                float cn = f_ * cp[idx] + i_ * g_;
                cp[idx] = cn;
                hp[idx] = __float2half_rn(o_ * ftanh(cn));
            }
        }
    }
}

// gather final token-phase h from the parity buffer of each row's last step
__global__ void __launch_bounds__(256)
gather_tok(const int* __restrict__ ntok)
{
    int idx = blockIdx.x * 256 + threadIdx.x;
    int n = idx >> 8;
    int L = ntok[n];
    g_instr_repr[idx] = (L > 0) ? g_h_tok[(L - 1) & 1][idx] : __half(0.0f);
}

// convert weights into gate-interleaved fp16 [jp][512]
__global__ void __launch_bounds__(256)
prep_weights(const float* __restrict__ WihT, const float* __restrict__ WhhT,
             const float* __restrict__ WihI, const float* __restrict__ WhhI)
{
    int idx = blockIdx.x * 256 + threadIdx.x;
    int jp = idx >> 9;
    int k  = idx & 511;
    int j  = (jp & 3) * 256 + (jp >> 2);
    float v = (k < 256) ? WihT[j * 256 + k] : WhhT[j * 256 + (k - 256)];
    g_W_tok[idx] = __float2half_rn(v);
    float u = (k < 256) ? WihI[j * 256 + k] : WhhI[j * 256 + (k - 256)];
    g_W_ins[idx] = __float2half_rn(u);
}

__global__ void __launch_bounds__(256)
prep_emb(const float* __restrict__ emb)
{
    int idx = blockIdx.x * 256 + threadIdx.x;
    g_emb_h[idx] = __float2half_rn(emb[idx]);
}

// counting sort by length (descending) + active-count table
__global__ void build_perm(const int* __restrict__ ntok,
                           const int* __restrict__ ninstr)
{
    __shared__ int hist[65];
    __shared__ int off[65];
    if (blockIdx.x == 0) {
        for (int i = threadIdx.x; i < 17; i += blockDim.x) hist[i] = 0;
        __syncthreads();
        for (int i = threadIdx.x; i < NTOK; i += blockDim.x)
            atomicAdd(&hist[ntok[i]], 1);
        __syncthreads();
        if (threadIdx.x == 0) {
            int acc = 0;
            for (int l = 16; l >= 0; --l) { off[l] = acc; acc += hist[l]; }
            for (int t = 0; t < TOKENS; ++t) g_cnt_tok[t] = off[t];
        }
        __syncthreads();
        for (int i = threadIdx.x; i < NTOK; i += blockDim.x) {
            int p = atomicAdd(&off[ntok[i]], 1);
            g_perm_tok[p] = i;
        }
    } else {
        for (int i = threadIdx.x; i < 65; i += blockDim.x) hist[i] = 0;
        __syncthreads();
        for (int i = threadIdx.x; i < BATCH; i += blockDim.x)
            atomicAdd(&hist[ninstr[i]], 1);
        __syncthreads();
        if (threadIdx.x == 0) {
            int acc = 0;
            for (int l = 64; l >= 0; --l) { off[l] = acc; acc += hist[l]; }
            for (int s = 0; s < INSTRS; ++s) g_cnt_ins[s] = off[s];
        }
        __syncthreads();
        for (int i = threadIdx.x; i < BATCH; i += blockDim.x) {
            int p = atomicAdd(&off[ninstr[i]], 1);
            g_perm_ins[p] = i;
        }
    }
}

__global__ void __launch_bounds__(256) zero_state()
{
    int idx = blockIdx.x * 256 + threadIdx.x;
    g_h_tok[0][idx] = __half(0.0f);
    g_h_tok[1][idx] = __half(0.0f);
    g_c_tok[idx]    = 0.0f;
    if (idx < BATCH * HID) {
        g_h_ins[0][idx] = __half(0.0f);
        g_h_ins[1][idx] = __half(0.0f);
        g_c_ins[idx]    = 0.0f;
    }
}

__global__ void __launch_bounds__(256)
final_linear(const int* __restrict__ ninstr,
             const float* __restrict__ linW,
             const float* __restrict__ linb,
             float* __restrict__ out)
{
    int b = blockIdx.x, tid = threadIdx.x;
    int L = ninstr[b];
    float h = (L > 0) ? __half2float(g_h_ins[(L - 1) & 1][(size_t)b * HID + tid]) : 0.0f;
    float v = h * linW[tid];
#pragma unroll
    for (int o = 16; o > 0; o >>= 1) v += __shfl_down_sync(0xffffffffu, v, o);
    __shared__ float red[8];
    if ((tid & 31) == 0) red[tid >> 5] = v;
    __syncthreads();
    if (tid < 8) {
        float s = red[tid];
#pragma unroll
        for (int o = 4; o > 0; o >>= 1) s += __shfl_down_sync(0xffu, s, o);
        if (tid == 0) out[b] = s + linb[0];
    }
}

extern "C" void kernel_launch(void* const* d_in, const int* in_sizes, int n_in,
                              void* d_out, int out_size)
{
    const int*   blocks = (const int*)d_in[0];
    const int*   ninstr = (const int*)d_in[1];
    const int*   ntok   = (const int*)d_in[2];
    const float* emb    = (const float*)d_in[3];
    const float* WihT   = (const float*)d_in[4];
    const float* WhhT   = (const float*)d_in[5];
    const float* bT     = (const float*)d_in[6];
    const float* WihI   = (const float*)d_in[7];
    const float* WhhI   = (const float*)d_in[8];
    const float* bI     = (const float*)d_in[9];
    const float* linW   = (const float*)d_in[10];
    const float* linb   = (const float*)d_in[11];
    float* out = (float*)d_out;
    (void)in_sizes; (void)n_in; (void)out_size;

    cudaFuncSetAttribute(tok_step, cudaFuncAttributeMaxDynamicSharedMemorySize, SMEM_BYTES);
    cudaFuncSetAttribute(ins_step, cudaFuncAttributeMaxDynamicSharedMemorySize, SMEM_BYTES);

    zero_state<<<NTOK * HID / 256, 256>>>();
    build_perm<<<2, 512>>>(ntok, ninstr);
    prep_weights<<<FOURH * KTOT / 256, 256>>>(WihT, WhhT, WihI, WhhI);
    prep_emb<<<4096 * EMB / 256, 256>>>(emb);

    for (int t = 0; t < TOKENS; ++t) {
        dim3 grid(NTOK / BM, FOURH / BN);          // 128 x 16, blocks self-trim
        tok_step<<<grid, 256, SMEM_BYTES>>>(t, blocks, bT, ntok);
    }
    gather_tok<<<NTOK * HID / 256, 256>>>(ntok);
    for (int s = 0; s < INSTRS; ++s) {
        dim3 grid(BATCH / BM, FOURH / BN);         // 2 x 16
        ins_step<<<grid, 256, SMEM_BYTES>>>(s, bI, ninstr);
    }
    final_linear<<<BATCH, 256>>>(ninstr, linW, linb, out);
}

// round 10
// speedup vs baseline: 1.1474x; 1.1474x over previous
#include <cuda_runtime.h>
#include <cuda_fp16.h>
#include <mma.h>
#include <cstdint>

using namespace nvcuda;

// ---------------- problem constants ----------------
#define BATCH   256
#define INSTRS  64
#define TOKENS  16
#define HID     256
#define EMB     256
#define FOURH   1024
#define KTOT    512
#define NTOK    (BATCH*INSTRS)   // 16384

// ---------------- GEMM tile config (round-5 proven: fp16 m16n16k16, BK=64, 2-stage) ----------------
#define BM 128
#define BN 64
#define BK 64
#define LDSH 72                  // BK + 8 pad (half; rows 144B, 16B aligned)
#define NK  (KTOT/BK)            // 8
#define CLD 68                   // epilogue Cs stride (floats)

// dynamic smem layout (bytes):
//  As: [2][BM*LDSH] half = 36864         (Cs float[128][68]=34816 overlays)
//  Bs: [2][BN*LDSH] half @ 36864, 18432
//  Aidx: int[128]        @ 55296
//  Arow: ptr[128]        @ 55808
#define SMEM_BYTES 56832

// ---------------- device state ----------------
// h ping-ponged by step parity: step t reads h[(t&1)^1], writes h[t&1].
__device__ __half g_h_tok[2][(size_t)NTOK * HID];
__device__ float  g_c_tok[(size_t)NTOK * HID];
__device__ __half g_h_ins[2][(size_t)BATCH * HID];
__device__ float  g_c_ins[(size_t)BATCH * HID];
__device__ __half g_instr_repr[(size_t)NTOK * HID];
__device__ int    g_perm_tok[NTOK];
__device__ int    g_cnt_tok[TOKENS];
__device__ int    g_perm_ins[BATCH];
__device__ int    g_cnt_ins[INSTRS];
// pre-converted fp16 operands
__device__ __half g_emb_h[(size_t)4096 * EMB];
__device__ __half g_W_tok[(size_t)FOURH * KTOT];   // [jp][512], gate-interleaved
__device__ __half g_W_ins[(size_t)FOURH * KTOT];

#define CP_ASYNC16(dst, src) \
    asm volatile("cp.async.cg.shared.global [%0], [%1], 16;" :: "r"(dst), "l"(src))
#define CP_COMMIT  asm volatile("cp.async.commit_group;")
#define CP_WAIT0   asm volatile("cp.async.wait_group 0;")

// fast, accurate-enough sigmoid/tanh (validated R9: rel_err 9.1e-5)
__device__ __forceinline__ float fsig(float x) { return 1.0f / (1.0f + __expf(-x)); }
__device__ __forceinline__ float ftanh(float x) {
    x = fminf(fmaxf(x, -15.0f), 15.0f);
    float e = __expf(2.0f * x);
    return (e - 1.0f) / (e + 1.0f);
}

// Fused LSTM step (round-5 structure): gate-interleaved fp16 GEMM + in-block cell update.
template<int MODE>
__global__ void __launch_bounds__(256)
fused_step(int t,
           const int*   __restrict__ tok,
           const float* __restrict__ bias,
           const int*   __restrict__ len_arr)
{
    const int cnt = (MODE == 0) ? g_cnt_tok[t] : g_cnt_ins[t];
    const int m0  = blockIdx.x * BM;
    if (m0 >= cnt) return;

    extern __shared__ char smraw[];
    __half*        As   = (__half*)smraw;                    // [2][BM*LDSH]
    __half*        Bs   = (__half*)(smraw + 36864);          // [2][BN*LDSH]
    int*           Aidx = (int*)(smraw + 55296);
    const __half** Arow = (const __half**)(smraw + 55808);
    float*         Cs   = (float*)smraw;                     // overlay

    const int n0  = blockIdx.y * BN;
    const int tid = threadIdx.x;
    const int wp  = t & 1;
    const int rp  = wp ^ 1;

    const int*    perm  = (MODE == 0) ? g_perm_tok : g_perm_ins;
    const __half* hbase = (MODE == 0) ? g_h_tok[rp] : g_h_ins[rp];
    const __half* Wbuf  = (MODE == 0) ? g_W_tok : g_W_ins;

    for (int r = tid; r < BM; r += 256) {
        int n = perm[m0 + r];
        Aidx[r] = n;
        if (MODE == 0)
            Arow[r] = g_emb_h + (size_t)__ldg(&tok[n * TOKENS + t]) * EMB;
        else
            Arow[r] = g_instr_repr + ((size_t)n * INSTRS + t) * HID;
    }
    __syncthreads();

    auto issue = [&](int kt, int buf) {
        __half* Ad = As + buf * BM * LDSH;
#pragma unroll
        for (int i = 0; i < 4; ++i) {
            int c  = tid + i * 256;
            int r  = c >> 3;
            int c8 = (c & 7) << 3;
            const __half* src = (kt < 4)
                ? Arow[r] + kt * BK + c8
                : hbase + (size_t)Aidx[r] * HID + (kt - 4) * BK + c8;
            uint32_t dst = (uint32_t)__cvta_generic_to_shared(Ad + r * LDSH + c8);
            CP_ASYNC16(dst, src);
        }
        __half* Bd = Bs + buf * BN * LDSH;
#pragma unroll
        for (int i = 0; i < 2; ++i) {
            int c  = tid + i * 256;
            int r  = c >> 3;
            int c8 = (c & 7) << 3;
            const __half* src = Wbuf + (size_t)(n0 + r) * KTOT + kt * BK + c8;
            uint32_t dst = (uint32_t)__cvta_generic_to_shared(Bd + r * LDSH + c8);
            CP_ASYNC16(dst, src);
        }
        CP_COMMIT;
    };

    wmma::fragment<wmma::accumulator, 16, 16, 16, float> cf[2][2];
#pragma unroll
    for (int mi = 0; mi < 2; ++mi)
#pragma unroll
        for (int ni = 0; ni < 2; ++ni)
            wmma::fill_fragment(cf[mi][ni], 0.0f);

    const int warp = tid >> 5;
    const int wm   = warp >> 1;
    const int wn   = warp & 1;

    const int nk_eff = (t == 0) ? 4 : NK;   // h==0 at step 0: skip h half of K exactly

    issue(0, 0);
    for (int kt = 0; kt < nk_eff; ++kt) {
        CP_WAIT0;
        __syncthreads();
        if (kt + 1 < nk_eff) issue(kt + 1, (kt + 1) & 1);
        const __half* Ab = As + (kt & 1) * BM * LDSH;
        const __half* Bb = Bs + (kt & 1) * BN * LDSH;
#pragma unroll
        for (int kk = 0; kk < BK; kk += 16) {
            wmma::fragment<wmma::matrix_a, 16, 16, 16, __half, wmma::row_major> a[2];
            wmma::fragment<wmma::matrix_b, 16, 16, 16, __half, wmma::col_major> b[2];
#pragma unroll
            for (int mi = 0; mi < 2; ++mi)
                wmma::load_matrix_sync(a[mi], Ab + (wm * 32 + mi * 16) * LDSH + kk, LDSH);
#pragma unroll
            for (int ni = 0; ni < 2; ++ni)
                wmma::load_matrix_sync(b[ni], Bb + (wn * 32 + ni * 16) * LDSH + kk, LDSH);
#pragma unroll
            for (int mi = 0; mi < 2; ++mi)
#pragma unroll
                for (int ni = 0; ni < 2; ++ni)
                    wmma::mma_sync(cf[mi][ni], a[mi], b[ni], cf[mi][ni]);
        }
    }

    // ---- epilogue: stage gates, apply cell update ----
    __syncthreads();
#pragma unroll
    for (int mi = 0; mi < 2; ++mi)
#pragma unroll
        for (int ni = 0; ni < 2; ++ni)
            wmma::store_matrix_sync(&Cs[(wm * 32 + mi * 16) * CLD + wn * 32 + ni * 16],
                                    cf[mi][ni], CLD, wmma::mem_row_major);
    __syncthreads();

    {
        int r = tid >> 1;
        int n = Aidx[r];
        int L = __ldg(&len_arr[n]);
        if (t < L) {
            __half* hp = (MODE == 0) ? g_h_tok[wp] : g_h_ins[wp];
            float*  cp = (MODE == 0) ? g_c_tok : g_c_ins;
            const bool last = (t == L - 1);
            int dg0 = (n0 >> 2) + (tid & 1) * 8;
#pragma unroll
            for (int i = 0; i < 8; ++i) {
                int dl = (tid & 1) * 8 + i;
                int dg = dg0 + i;
                float gi = Cs[r * CLD + dl * 4 + 0] + __ldg(&bias[dg]);
                float gf = Cs[r * CLD + dl * 4 + 1] + __ldg(&bias[256 + dg]);
                float gg = Cs[r * CLD + dl * 4 + 2] + __ldg(&bias[512 + dg]);
                float go = Cs[r * CLD + dl * 4 + 3] + __ldg(&bias[768 + dg]);
                float i_ = fsig(gi);
                float f_ = fsig(gf);
                float g_ = ftanh(gg);
                float o_ = fsig(go);
                size_t idx = (size_t)n * HID + dg;
                float cn = f_ * cp[idx] + i_ * g_;
                cp[idx] = cn;
                __half hv = __float2half_rn(o_ * ftanh(cn));
                hp[idx] = hv;
                // fused gather: token phase writes its final h straight to instr_repr
                if (MODE == 0 && last) g_instr_repr[idx] = hv;
            }
        }
    }
}

// merged prep: convert weights (gate-interleaved [jp][512]) + embedding to fp16
__global__ void __launch_bounds__(256)
prep_all(const float* __restrict__ WihT, const float* __restrict__ WhhT,
         const float* __restrict__ WihI, const float* __restrict__ WhhI,
         const float* __restrict__ emb)
{
    int idx = blockIdx.x * 256 + threadIdx.x;      // grid covers 4096*256
    g_emb_h[idx] = __float2half_rn(emb[idx]);
    if (idx < FOURH * KTOT) {
        int jp = idx >> 9;
        int k  = idx & 511;
        int j  = (jp & 3) * 256 + (jp >> 2);       // gate*256 + d
        float v = (k < 256) ? WihT[j * 256 + k] : WhhT[j * 256 + (k - 256)];
        g_W_tok[idx] = __float2half_rn(v);
        float u = (k < 256) ? WihI[j * 256 + k] : WhhI[j * 256 + (k - 256)];
        g_W_ins[idx] = __float2half_rn(u);
    }
}

// counting sort by length (descending) + active-count table
__global__ void build_perm(const int* __restrict__ ntok,
                           const int* __restrict__ ninstr)
{
    __shared__ int hist[65];
    __shared__ int off[65];
    if (blockIdx.x == 0) {
        for (int i = threadIdx.x; i < 17; i += blockDim.x) hist[i] = 0;
        __syncthreads();
        for (int i = threadIdx.x; i < NTOK; i += blockDim.x)
            atomicAdd(&hist[ntok[i]], 1);
        __syncthreads();
        if (threadIdx.x == 0) {
            int acc = 0;
            for (int l = 16; l >= 0; --l) { off[l] = acc; acc += hist[l]; }
            for (int t = 0; t < TOKENS; ++t) g_cnt_tok[t] = off[t];
        }
        __syncthreads();
        for (int i = threadIdx.x; i < NTOK; i += blockDim.x) {
            int p = atomicAdd(&off[ntok[i]], 1);
            g_perm_tok[p] = i;
        }
    } else {
        for (int i = threadIdx.x; i < 65; i += blockDim.x) hist[i] = 0;
        __syncthreads();
        for (int i = threadIdx.x; i < BATCH; i += blockDim.x)
            atomicAdd(&hist[ninstr[i]], 1);
        __syncthreads();
        if (threadIdx.x == 0) {
            int acc = 0;
            for (int l = 64; l >= 0; --l) { off[l] = acc; acc += hist[l]; }
            for (int s = 0; s < INSTRS; ++s) g_cnt_ins[s] = off[s];
        }
        __syncthreads();
        for (int i = threadIdx.x; i < BATCH; i += blockDim.x) {
            int p = atomicAdd(&off[ninstr[i]], 1);
            g_perm_ins[p] = i;
        }
    }
}

__global__ void __launch_bounds__(256) zero_state()
{
    int idx = blockIdx.x * 256 + threadIdx.x;   // grid covers NTOK*HID
    g_h_tok[0][idx] = __half(0.0f);
    g_h_tok[1][idx] = __half(0.0f);
    g_c_tok[idx]    = 0.0f;
    g_instr_repr[idx] = __half(0.0f);           // rows with len==0 keep zeros
    if (idx < BATCH * HID) {
        g_h_ins[0][idx] = __half(0.0f);
        g_h_ins[1][idx] = __half(0.0f);
        g_c_ins[idx]    = 0.0f;
    }
}

__global__ void __launch_bounds__(256)
final_linear(const int* __restrict__ ninstr,
             const float* __restrict__ linW,
             const float* __restrict__ linb,
             float* __restrict__ out)
{
    int b = blockIdx.x, tid = threadIdx.x;
    int L = ninstr[b];
    float h = (L > 0) ? __half2float(g_h_ins[(L - 1) & 1][(size_t)b * HID + tid]) : 0.0f;
    float v = h * linW[tid];
#pragma unroll
    for (int o = 16; o > 0; o >>= 1) v += __shfl_down_sync(0xffffffffu, v, o);
    __shared__ float red[8];
    if ((tid & 31) == 0) red[tid >> 5] = v;
    __syncthreads();
    if (tid < 8) {
        float s = red[tid];
#pragma unroll
        for (int o = 4; o > 0; o >>= 1) s += __shfl_down_sync(0xffu, s, o);
        if (tid == 0) out[b] = s + linb[0];
    }
}

extern "C" void kernel_launch(void* const* d_in, const int* in_sizes, int n_in,
                              void* d_out, int out_size)
{
    const int*   blocks = (const int*)d_in[0];
    const int*   ninstr = (const int*)d_in[1];
    const int*   ntok   = (const int*)d_in[2];
    const float* emb    = (const float*)d_in[3];
    const float* WihT   = (const float*)d_in[4];
    const float* WhhT   = (const float*)d_in[5];
    const float* bT     = (const float*)d_in[6];
    const float* WihI   = (const float*)d_in[7];
    const float* WhhI   = (const float*)d_in[8];
    const float* bI     = (const float*)d_in[9];
    const float* linW   = (const float*)d_in[10];
    const float* linb   = (const float*)d_in[11];
    float* out = (float*)d_out;
    (void)in_sizes; (void)n_in; (void)out_size;

    cudaFuncSetAttribute(fused_step<0>, cudaFuncAttributeMaxDynamicSharedMemorySize, SMEM_BYTES);
    cudaFuncSetAttribute(fused_step<1>, cudaFuncAttributeMaxDynamicSharedMemorySize, SMEM_BYTES);

    zero_state<<<NTOK * HID / 256, 256>>>();
    build_perm<<<2, 512>>>(ntok, ninstr);
    prep_all<<<4096 * EMB / 256, 256>>>(WihT, WhhT, WihI, WhhI, emb);

    for (int t = 0; t < TOKENS; ++t) {
        dim3 grid(NTOK / BM, FOURH / BN);          // 128 x 16, blocks self-trim
        fused_step<0><<<grid, 256, SMEM_BYTES>>>(t, blocks, bT, ntok);
    }
    for (int s = 0; s < INSTRS; ++s) {
        dim3 grid(BATCH / BM, FOURH / BN);         // 2 x 16
        fused_step<1><<<grid, 256, SMEM_BYTES>>>(s, nullptr, bI, ninstr);
    }
    final_linear<<<BATCH, 256>>>(ninstr, linW, linb, out);
}